// round 10
// baseline (speedup 1.0000x reference)
#include <cuda_runtime.h>
#include <math.h>
#include <stdint.h>

namespace {
constexpr int Bb = 2;          // batch
constexpr int Sn = 2048;       // sequence
constexpr int Hh = 8;          // heads
constexpr int Dd = 64;         // head dim
constexpr int Dm = 512;        // Hh*Dd
constexpr int Rows = Bb * Sn;  // 4096
constexpr float EPSv = 1e-4f;
constexpr float SCALEv = 0.125f;       // 64^-0.5
constexpr float LOG2E = 1.4426950408889634f;
}

// Scratch (8 MB each) — device globals, no runtime allocation.
__device__ float g_q[Rows * Dm];
__device__ float g_k[Rows * Dm];
__device__ float g_v[Rows * Dm];
__device__ float g_o[Rows * Dm];

// ---------------------------------------------------------------------------
// helpers
// ---------------------------------------------------------------------------
__device__ __forceinline__ uint32_t f2tf(float f) {
    uint32_t u;
    asm("cvt.rna.tf32.f32 %0, %1;" : "=r"(u) : "f"(f));
    return u;
}
__device__ __forceinline__ float exp2a(float x) {
    float y;
    asm("ex2.approx.ftz.f32 %0, %1;" : "=f"(y) : "f"(x));
    return y;
}
__device__ __forceinline__ void mma_tf32(float c[4], const uint32_t a[4],
                                         uint32_t b0, uint32_t b1) {
    asm volatile(
        "mma.sync.aligned.m16n8k8.row.col.f32.tf32.tf32.f32 "
        "{%0,%1,%2,%3}, {%4,%5,%6,%7}, {%8,%9}, {%0,%1,%2,%3};\n"
        : "+f"(c[0]), "+f"(c[1]), "+f"(c[2]), "+f"(c[3])
        : "r"(a[0]), "r"(a[1]), "r"(a[2]), "r"(a[3]), "r"(b0), "r"(b1));
}

// ---------------------------------------------------------------------------
// C[M,Nc] = A[M,K] @ B[Nc,K]^T (row-major), tf32 tensor-core GEMM.
// Tile 128x64, BK=16, 256 threads = 8 warps, each warp a 16x64 slab
// (1 m-tile x 8 n-tiles) so a row's full 64-col head segment lives in one
// warp quad -> fused RMS-norm stays shuffle-only. Double-buffered smem.
// Grid (Nc/64, M/128) = 256 CTAs -> all 148 SMs busy, 2 CTAs/SM.
// ---------------------------------------------------------------------------
__global__ __launch_bounds__(256, 2) void gemm_tf32(
    const float* __restrict__ A, const float* __restrict__ Bw,
    float* __restrict__ C, int M, int Nc, int K, float norm_mul)
{
    __shared__ uint32_t As[2][128 * 20];
    __shared__ uint32_t Bs[2][64 * 20];

    const int tid  = threadIdx.x;
    const int lane = tid & 31, wid = tid >> 5;     // 8 warps
    const int grp  = lane >> 2, tg = lane & 3;
    const int m0   = blockIdx.y * 128, n0 = blockIdx.x * 64;
    const int lr   = tid >> 2, lc4 = (tid & 3) * 4;

    float c[8][4];
    #pragma unroll
    for (int nt = 0; nt < 8; ++nt)
        #pragma unroll
        for (int i = 0; i < 4; ++i) c[nt][i] = 0.0f;

    float4 ra[2], rb;
    ra[0] = *(const float4*)&A [(size_t)(m0 + lr)      * K + lc4];
    ra[1] = *(const float4*)&A [(size_t)(m0 + lr + 64) * K + lc4];
    rb    = *(const float4*)&Bw[(size_t)(n0 + lr)      * K + lc4];
    {
        uint32_t* pa = &As[0][lr * 20 + lc4];
        pa[0] = f2tf(ra[0].x); pa[1] = f2tf(ra[0].y);
        pa[2] = f2tf(ra[0].z); pa[3] = f2tf(ra[0].w);
        uint32_t* pa2 = &As[0][(lr + 64) * 20 + lc4];
        pa2[0] = f2tf(ra[1].x); pa2[1] = f2tf(ra[1].y);
        pa2[2] = f2tf(ra[1].z); pa2[3] = f2tf(ra[1].w);
        uint32_t* pb = &Bs[0][lr * 20 + lc4];
        pb[0] = f2tf(rb.x); pb[1] = f2tf(rb.y);
        pb[2] = f2tf(rb.z); pb[3] = f2tf(rb.w);
    }
    __syncthreads();

    int p = 0;
    for (int k0 = 0; k0 < K; k0 += 16) {
        const bool has_next = (k0 + 16) < K;
        if (has_next) {
            ra[0] = *(const float4*)&A [(size_t)(m0 + lr)      * K + k0 + 16 + lc4];
            ra[1] = *(const float4*)&A [(size_t)(m0 + lr + 64) * K + k0 + 16 + lc4];
            rb    = *(const float4*)&Bw[(size_t)(n0 + lr)      * K + k0 + 16 + lc4];
        }

        #pragma unroll
        for (int ks = 0; ks < 2; ++ks) {
            uint32_t a[4];
            const uint32_t* q = &As[p][(wid * 16 + grp) * 20 + ks * 8 + tg];
            a[0] = q[0];       a[2] = q[4];
            a[1] = q[20 * 8];  a[3] = q[20 * 8 + 4];
            #pragma unroll
            for (int nt = 0; nt < 8; ++nt) {
                const uint32_t* qb = &Bs[p][(nt * 8 + grp) * 20 + ks * 8 + tg];
                mma_tf32(c[nt], a, qb[0], qb[4]);
            }
        }

        if (has_next) {
            uint32_t* pa = &As[p ^ 1][lr * 20 + lc4];
            pa[0] = f2tf(ra[0].x); pa[1] = f2tf(ra[0].y);
            pa[2] = f2tf(ra[0].z); pa[3] = f2tf(ra[0].w);
            uint32_t* pa2 = &As[p ^ 1][(lr + 64) * 20 + lc4];
            pa2[0] = f2tf(ra[1].x); pa2[1] = f2tf(ra[1].y);
            pa2[2] = f2tf(ra[1].z); pa2[3] = f2tf(ra[1].w);
            uint32_t* pb = &Bs[p ^ 1][lr * 20 + lc4];
            pb[0] = f2tf(rb.x); pb[1] = f2tf(rb.y);
            pb[2] = f2tf(rb.z); pb[3] = f2tf(rb.w);
        }
        __syncthreads();
        p ^= 1;
    }

    // Epilogue: optional fused RMS-magnitude norm over each row's 64-col
    // head segment (warp-quad holds the full segment), then store.
    float sc0 = 1.0f, sc1 = 1.0f;
    if (norm_mul != 0.0f) {
        float ss0 = 0.0f, ss1 = 0.0f;
        #pragma unroll
        for (int nt = 0; nt < 8; ++nt) {
            ss0 += c[nt][0] * c[nt][0] + c[nt][1] * c[nt][1];
            ss1 += c[nt][2] * c[nt][2] + c[nt][3] * c[nt][3];
        }
        ss0 += __shfl_xor_sync(0xffffffffu, ss0, 1);
        ss0 += __shfl_xor_sync(0xffffffffu, ss0, 2);
        ss1 += __shfl_xor_sync(0xffffffffu, ss1, 1);
        ss1 += __shfl_xor_sync(0xffffffffu, ss1, 2);
        sc0 = norm_mul / (sqrtf(ss0 * (1.0f / 64.0f)) + EPSv);
        sc1 = norm_mul / (sqrtf(ss1 * (1.0f / 64.0f)) + EPSv);
    }
    int row = m0 + wid * 16 + grp;
    #pragma unroll
    for (int nt = 0; nt < 8; ++nt) {
        int col = n0 + nt * 8 + tg * 2;
        *(float2*)&C[(size_t)row * Nc + col] =
            make_float2(c[nt][0] * sc0, c[nt][1] * sc0);
        *(float2*)&C[(size_t)(row + 8) * Nc + col] =
            make_float2(c[nt][2] * sc1, c[nt][3] * sc1);
    }
}

// ---------------------------------------------------------------------------
// Flash attention, tf32 tensor cores, cosine-bounded softmax (NO max
// tracking: post-norm scores are bounded by 8*log2e, exp2 cannot overflow,
// and softmax is shift-invariant so results are identical).
// CTA = 64 queries of one (b,h), 4 warps x 16 rows. Grid = 512 CTAs,
// 3 CTAs/SM (70.7 KB smem each) -> ~14 warps/SM chip-wide.
// Smem: Qs[64][68] + Ks[64][68] + Ps[64][68] + Vs[64][72] = 70656 B.
// ---------------------------------------------------------------------------
__global__ __launch_bounds__(128, 3) void attn_tf32()
{
    extern __shared__ uint32_t sm[];
    uint32_t* Qs = sm;                 // [64][68]
    uint32_t* Ks = Qs + 64 * 68;       // [64][68]
    uint32_t* Ps = Ks + 64 * 68;       // [64][68]
    uint32_t* Vs = Ps + 64 * 68;       // [64][72]

    const int tid  = threadIdx.x;
    const int lane = tid & 31, wid = tid >> 5;
    const int grp  = lane >> 2, tg = lane & 3;
    const int row0 = wid * 16;
    const int qt = blockIdx.x, h = blockIdx.y, b = blockIdx.z;
    const int qrow0 = b * Sn + qt * 64;
    const int hoff  = h * Dd;

    // Load Q tile: 64x64 floats = 1024 float4, 8 per thread.
    #pragma unroll
    for (int it = 0; it < 8; ++it) {
        int lin = tid + it * 128;
        int r = lin >> 4, c4 = (lin & 15) * 4;
        float4 v = *(const float4*)&g_q[(size_t)(qrow0 + r) * Dm + hoff + c4];
        uint32_t* pq = &Qs[r * 68 + c4];
        pq[0] = f2tf(v.x); pq[1] = f2tf(v.y); pq[2] = f2tf(v.z); pq[3] = f2tf(v.w);
    }

    float o[8][4];
    float l0 = 0.0f, l1 = 0.0f;  // per-thread partial row sums
    #pragma unroll
    for (int nt = 0; nt < 8; ++nt)
        #pragma unroll
        for (int i = 0; i < 4; ++i) o[nt][i] = 0.0f;

    for (int kt = 0; kt < Sn / 64; ++kt) {
        __syncthreads();   // K/V reuse fence (also covers initial Q staging)
        const int krow0 = b * Sn + kt * 64;
        #pragma unroll
        for (int it = 0; it < 8; ++it) {
            int lin = tid + it * 128;
            int r = lin >> 4, c4 = (lin & 15) * 4;
            float4 kv = *(const float4*)&g_k[(size_t)(krow0 + r) * Dm + hoff + c4];
            uint32_t* pk = &Ks[r * 68 + c4];
            pk[0] = f2tf(kv.x); pk[1] = f2tf(kv.y);
            pk[2] = f2tf(kv.z); pk[3] = f2tf(kv.w);
            float4 vv = *(const float4*)&g_v[(size_t)(krow0 + r) * Dm + hoff + c4];
            uint32_t* pv = &Vs[r * 72 + c4];
            pv[0] = f2tf(vv.x); pv[1] = f2tf(vv.y);
            pv[2] = f2tf(vv.z); pv[3] = f2tf(vv.w);
        }
        __syncthreads();

        // ---- S = Q K^T (scale*log2e folded into Q) ----
        float s[8][4];
        #pragma unroll
        for (int nt = 0; nt < 8; ++nt)
            #pragma unroll
            for (int i = 0; i < 4; ++i) s[nt][i] = 0.0f;

        #pragma unroll
        for (int ks = 0; ks < 8; ++ks) {
            uint32_t a[4];
            const uint32_t* pq = &Qs[(row0 + grp) * 68 + ks * 8 + tg];
            a[0] = pq[0];       a[2] = pq[4];
            a[1] = pq[68 * 8];  a[3] = pq[68 * 8 + 4];
            #pragma unroll
            for (int nt = 0; nt < 8; ++nt) {
                const uint32_t* pk = &Ks[(nt * 8 + grp) * 68 + ks * 8 + tg];
                mma_tf32(s[nt], a, pk[0], pk[4]);
            }
        }

        // ---- exp2, accumulate l, stash P (no max/rescale needed) ----
        #pragma unroll
        for (int nt = 0; nt < 8; ++nt) {
            float p0 = exp2a(s[nt][0]);
            float p1 = exp2a(s[nt][1]);
            float p2 = exp2a(s[nt][2]);
            float p3 = exp2a(s[nt][3]);
            l0 += p0 + p1;
            l1 += p2 + p3;
            uint32_t* pp = &Ps[(row0 + grp) * 68 + nt * 8 + tg * 2];
            pp[0]          = f2tf(p0);
            pp[1]          = f2tf(p1);
            pp[68 * 8]     = f2tf(p2);
            pp[68 * 8 + 1] = f2tf(p3);
        }
        __syncwarp();   // P written/read by this warp's rows only

        // ---- O += P V ----
        #pragma unroll
        for (int ks = 0; ks < 8; ++ks) {
            uint32_t a[4];
            const uint32_t* pp = &Ps[(row0 + grp) * 68 + ks * 8 + tg];
            a[0] = pp[0];       a[2] = pp[4];
            a[1] = pp[68 * 8];  a[3] = pp[68 * 8 + 4];
            #pragma unroll
            for (int nt = 0; nt < 8; ++nt) {
                uint32_t b0 = Vs[(ks * 8 + tg) * 72 + nt * 8 + grp];
                uint32_t b1 = Vs[(ks * 8 + tg + 4) * 72 + nt * 8 + grp];
                mma_tf32(o[nt], a, b0, b1);
            }
        }
    }

    // epilogue: reduce l across the quad, normalize, store
    l0 += __shfl_xor_sync(0xffffffffu, l0, 1);
    l0 += __shfl_xor_sync(0xffffffffu, l0, 2);
    l1 += __shfl_xor_sync(0xffffffffu, l1, 1);
    l1 += __shfl_xor_sync(0xffffffffu, l1, 2);
    float inv0 = 1.0f / l0;
    float inv1 = 1.0f / l1;
    int row = qrow0 + row0 + grp;
    #pragma unroll
    for (int nt = 0; nt < 8; ++nt) {
        int col = hoff + nt * 8 + tg * 2;
        *(float2*)&g_o[(size_t)row * Dm + col] =
            make_float2(o[nt][0] * inv0, o[nt][1] * inv0);
        *(float2*)&g_o[(size_t)(row + 8) * Dm + col] =
            make_float2(o[nt][2] * inv1, o[nt][3] * inv1);
    }
}

// ---------------------------------------------------------------------------
extern "C" void kernel_launch(void* const* d_in, const int* in_sizes, int n_in,
                              void* d_out, int out_size)
{
    (void)in_sizes; (void)n_in; (void)out_size;
    const float* x    = (const float*)d_in[0];
    const float* Wq   = (const float*)d_in[1];
    const float* Wkv  = (const float*)d_in[2];
    const float* Wout = (const float*)d_in[3];
    float* out = (float*)d_out;

    float *q, *k, *v, *o;
    cudaGetSymbolAddress((void**)&q, g_q);
    cudaGetSymbolAddress((void**)&k, g_k);
    cudaGetSymbolAddress((void**)&v, g_v);
    cudaGetSymbolAddress((void**)&o, g_o);

    cudaFuncSetAttribute(attn_tf32,
                         cudaFuncAttributeMaxDynamicSharedMemorySize, 70656);

    dim3 blk(256);
    dim3 ggrid(Dm / 64, Rows / 128);   // (8, 32) = 256 CTAs

    // Projections (tf32 tensor cores). RMS-norm fused into Q/K epilogues:
    // Q also folds scale*log2e so softmax runs directly in exp2 domain.
    gemm_tf32<<<ggrid, blk>>>(x, Wq, q, Rows, Dm, Dm, SCALEv * LOG2E);
    gemm_tf32<<<ggrid, blk>>>(x, Wkv, k, Rows, Dm, Dm, 1.0f);
    gemm_tf32<<<ggrid, blk>>>(x, Wkv + (size_t)Dm * Dm, v, Rows, Dm, Dm, 0.0f);

    // Attention: 512 CTAs, 3 CTAs/SM
    attn_tf32<<<dim3(Sn / 64, Hh, Bb), 128, 70656>>>();

    // Output projection
    gemm_tf32<<<ggrid, blk>>>(o, Wout, out, Rows, Dm, Dm, 0.0f);
}

// round 14
// speedup vs baseline: 1.1457x; 1.1457x over previous
#include <cuda_runtime.h>
#include <math.h>
#include <stdint.h>

namespace {
constexpr int Bb = 2;          // batch
constexpr int Sn = 2048;       // sequence
constexpr int Hh = 8;          // heads
constexpr int Dd = 64;         // head dim
constexpr int Dm = 512;        // Hh*Dd
constexpr int Rows = Bb * Sn;  // 4096
constexpr float EPSv = 1e-4f;
constexpr float SCALEv = 0.125f;       // 64^-0.5
constexpr float LOG2E = 1.4426950408889634f;
}

// Scratch (8 MB each) — device globals, no runtime allocation.
__device__ float g_q[Rows * Dm];
__device__ float g_k[Rows * Dm];
__device__ float g_v[Rows * Dm];
__device__ float g_o[Rows * Dm];

// ---------------------------------------------------------------------------
// helpers
// ---------------------------------------------------------------------------
__device__ __forceinline__ uint32_t f2tf(float f) {
    uint32_t u;
    asm("cvt.rna.tf32.f32 %0, %1;" : "=r"(u) : "f"(f));
    return u;
}
__device__ __forceinline__ float exp2a(float x) {
    float y;
    asm("ex2.approx.ftz.f32 %0, %1;" : "=f"(y) : "f"(x));
    return y;
}
__device__ __forceinline__ void mma_tf32(float c[4], const uint32_t a[4],
                                         uint32_t b0, uint32_t b1) {
    asm volatile(
        "mma.sync.aligned.m16n8k8.row.col.f32.tf32.tf32.f32 "
        "{%0,%1,%2,%3}, {%4,%5,%6,%7}, {%8,%9}, {%0,%1,%2,%3};\n"
        : "+f"(c[0]), "+f"(c[1]), "+f"(c[2]), "+f"(c[3])
        : "r"(a[0]), "r"(a[1]), "r"(a[2]), "r"(a[3]), "r"(b0), "r"(b1));
}

// ---------------------------------------------------------------------------
// C[M,Nc] = A[M,K] @ B[Nc,K]^T (row-major), tf32 tensor-core GEMM.
// Tile 128x64, BK=16, 256 threads = 8 warps, each warp a 16x64 slab
// (1 m-tile x 8 n-tiles) so a row's full 64-col head segment lives in one
// warp quad -> fused RMS-norm stays shuffle-only. Double-buffered smem.
// Grid (Nc/64, M/128) = 256 CTAs -> all 148 SMs busy, 2 CTAs/SM.
// ---------------------------------------------------------------------------
__global__ __launch_bounds__(256, 2) void gemm_tf32(
    const float* __restrict__ A, const float* __restrict__ Bw,
    float* __restrict__ C, int M, int Nc, int K, float norm_mul)
{
    __shared__ uint32_t As[2][128 * 20];
    __shared__ uint32_t Bs[2][64 * 20];

    const int tid  = threadIdx.x;
    const int lane = tid & 31, wid = tid >> 5;     // 8 warps
    const int grp  = lane >> 2, tg = lane & 3;
    const int m0   = blockIdx.y * 128, n0 = blockIdx.x * 64;
    const int lr   = tid >> 2, lc4 = (tid & 3) * 4;

    float c[8][4];
    #pragma unroll
    for (int nt = 0; nt < 8; ++nt)
        #pragma unroll
        for (int i = 0; i < 4; ++i) c[nt][i] = 0.0f;

    float4 ra[2], rb;
    ra[0] = *(const float4*)&A [(size_t)(m0 + lr)      * K + lc4];
    ra[1] = *(const float4*)&A [(size_t)(m0 + lr + 64) * K + lc4];
    rb    = *(const float4*)&Bw[(size_t)(n0 + lr)      * K + lc4];
    {
        uint32_t* pa = &As[0][lr * 20 + lc4];
        pa[0] = f2tf(ra[0].x); pa[1] = f2tf(ra[0].y);
        pa[2] = f2tf(ra[0].z); pa[3] = f2tf(ra[0].w);
        uint32_t* pa2 = &As[0][(lr + 64) * 20 + lc4];
        pa2[0] = f2tf(ra[1].x); pa2[1] = f2tf(ra[1].y);
        pa2[2] = f2tf(ra[1].z); pa2[3] = f2tf(ra[1].w);
        uint32_t* pb = &Bs[0][lr * 20 + lc4];
        pb[0] = f2tf(rb.x); pb[1] = f2tf(rb.y);
        pb[2] = f2tf(rb.z); pb[3] = f2tf(rb.w);
    }
    __syncthreads();

    int p = 0;
    for (int k0 = 0; k0 < K; k0 += 16) {
        const bool has_next = (k0 + 16) < K;
        if (has_next) {
            ra[0] = *(const float4*)&A [(size_t)(m0 + lr)      * K + k0 + 16 + lc4];
            ra[1] = *(const float4*)&A [(size_t)(m0 + lr + 64) * K + k0 + 16 + lc4];
            rb    = *(const float4*)&Bw[(size_t)(n0 + lr)      * K + k0 + 16 + lc4];
        }

        #pragma unroll
        for (int ks = 0; ks < 2; ++ks) {
            uint32_t a[4];
            const uint32_t* q = &As[p][(wid * 16 + grp) * 20 + ks * 8 + tg];
            a[0] = q[0];       a[2] = q[4];
            a[1] = q[20 * 8];  a[3] = q[20 * 8 + 4];
            #pragma unroll
            for (int nt = 0; nt < 8; ++nt) {
                const uint32_t* qb = &Bs[p][(nt * 8 + grp) * 20 + ks * 8 + tg];
                mma_tf32(c[nt], a, qb[0], qb[4]);
            }
        }

        if (has_next) {
            uint32_t* pa = &As[p ^ 1][lr * 20 + lc4];
            pa[0] = f2tf(ra[0].x); pa[1] = f2tf(ra[0].y);
            pa[2] = f2tf(ra[0].z); pa[3] = f2tf(ra[0].w);
            uint32_t* pa2 = &As[p ^ 1][(lr + 64) * 20 + lc4];
            pa2[0] = f2tf(ra[1].x); pa2[1] = f2tf(ra[1].y);
            pa2[2] = f2tf(ra[1].z); pa2[3] = f2tf(ra[1].w);
            uint32_t* pb = &Bs[p ^ 1][lr * 20 + lc4];
            pb[0] = f2tf(rb.x); pb[1] = f2tf(rb.y);
            pb[2] = f2tf(rb.z); pb[3] = f2tf(rb.w);
        }
        __syncthreads();
        p ^= 1;
    }

    // Epilogue: optional fused RMS-magnitude norm over each row's 64-col
    // head segment (warp-quad holds the full segment), then store.
    float sc0 = 1.0f, sc1 = 1.0f;
    if (norm_mul != 0.0f) {
        float ss0 = 0.0f, ss1 = 0.0f;
        #pragma unroll
        for (int nt = 0; nt < 8; ++nt) {
            ss0 += c[nt][0] * c[nt][0] + c[nt][1] * c[nt][1];
            ss1 += c[nt][2] * c[nt][2] + c[nt][3] * c[nt][3];
        }
        ss0 += __shfl_xor_sync(0xffffffffu, ss0, 1);
        ss0 += __shfl_xor_sync(0xffffffffu, ss0, 2);
        ss1 += __shfl_xor_sync(0xffffffffu, ss1, 1);
        ss1 += __shfl_xor_sync(0xffffffffu, ss1, 2);
        sc0 = norm_mul / (sqrtf(ss0 * (1.0f / 64.0f)) + EPSv);
        sc1 = norm_mul / (sqrtf(ss1 * (1.0f / 64.0f)) + EPSv);
    }
    int row = m0 + wid * 16 + grp;
    #pragma unroll
    for (int nt = 0; nt < 8; ++nt) {
        int col = n0 + nt * 8 + tg * 2;
        *(float2*)&C[(size_t)row * Nc + col] =
            make_float2(c[nt][0] * sc0, c[nt][1] * sc0);
        *(float2*)&C[(size_t)(row + 8) * Nc + col] =
            make_float2(c[nt][2] * sc1, c[nt][3] * sc1);
    }
}

// ---------------------------------------------------------------------------
// Flash attention, tf32 tensor cores, cosine-bounded softmax.
// Post-norm scores are bounded (|s| <= 8*log2e ~ 11.6): exp2 can neither
// overflow nor destructively underflow, and softmax is shift-invariant, so
// NO running-max tracking is needed — results are mathematically identical.
// CTA = 128 queries of one (b,h), 4 warps x 32 rows (high MMA reuse per
// LDS fragment — the R9 16-row retile regressed). 2 CTAs/SM.
// Dynamic smem = (128+64+128)*68*4 + 64*72*4 = 105472 B.
// ---------------------------------------------------------------------------
__global__ __launch_bounds__(128, 2) void attn_tf32()
{
    extern __shared__ uint32_t sm[];
    uint32_t* Qs = sm;                 // [128][68]
    uint32_t* Ks = Qs + 128 * 68;      // [64][68]
    uint32_t* Ps = Ks + 64 * 68;       // [128][68]
    uint32_t* Vs = Ps + 128 * 68;      // [64][72]

    const int tid  = threadIdx.x;
    const int lane = tid & 31, wid = tid >> 5;
    const int grp  = lane >> 2, tg = lane & 3;
    const int row0 = wid * 32;
    const int qt = blockIdx.x, h = blockIdx.y, b = blockIdx.z;
    const int qrow0 = b * Sn + qt * 128;
    const int hoff  = h * Dd;

    // Load Q tile: 128x64 floats = 2048 float4, 16 per thread.
    #pragma unroll
    for (int it = 0; it < 16; ++it) {
        int lin = tid + it * 128;
        int r = lin >> 4, c4 = (lin & 15) * 4;
        float4 v = *(const float4*)&g_q[(size_t)(qrow0 + r) * Dm + hoff + c4];
        uint32_t* p = &Qs[r * 68 + c4];
        p[0] = f2tf(v.x); p[1] = f2tf(v.y); p[2] = f2tf(v.z); p[3] = f2tf(v.w);
    }

    float o[2][8][4];
    float lacc[2][2] = {};   // per-thread partial row sums [mt][rh]
    #pragma unroll
    for (int mt = 0; mt < 2; ++mt)
        #pragma unroll
        for (int nt = 0; nt < 8; ++nt)
            #pragma unroll
            for (int i = 0; i < 4; ++i) o[mt][nt][i] = 0.0f;

    for (int kt = 0; kt < Sn / 64; ++kt) {
        __syncthreads();   // K/V reuse fence (also covers initial Q staging)
        const int krow0 = b * Sn + kt * 64;
        #pragma unroll
        for (int it = 0; it < 8; ++it) {
            int lin = tid + it * 128;
            int r = lin >> 4, c4 = (lin & 15) * 4;
            float4 kv = *(const float4*)&g_k[(size_t)(krow0 + r) * Dm + hoff + c4];
            uint32_t* pk = &Ks[r * 68 + c4];
            pk[0] = f2tf(kv.x); pk[1] = f2tf(kv.y);
            pk[2] = f2tf(kv.z); pk[3] = f2tf(kv.w);
            float4 vv = *(const float4*)&g_v[(size_t)(krow0 + r) * Dm + hoff + c4];
            uint32_t* pv = &Vs[r * 72 + c4];
            pv[0] = f2tf(vv.x); pv[1] = f2tf(vv.y);
            pv[2] = f2tf(vv.z); pv[3] = f2tf(vv.w);
        }
        __syncthreads();

        // ---- S = Q K^T (scale*log2e folded into Q) ----
        float s[2][8][4];
        #pragma unroll
        for (int mt = 0; mt < 2; ++mt)
            #pragma unroll
            for (int nt = 0; nt < 8; ++nt)
                #pragma unroll
                for (int i = 0; i < 4; ++i) s[mt][nt][i] = 0.0f;

        #pragma unroll
        for (int ks = 0; ks < 8; ++ks) {
            uint32_t a[2][4];
            #pragma unroll
            for (int mt = 0; mt < 2; ++mt) {
                const uint32_t* p = &Qs[(row0 + mt * 16 + grp) * 68 + ks * 8 + tg];
                a[mt][0] = p[0];       a[mt][2] = p[4];
                a[mt][1] = p[68 * 8];  a[mt][3] = p[68 * 8 + 4];
            }
            #pragma unroll
            for (int nt = 0; nt < 8; ++nt) {
                const uint32_t* p = &Ks[(nt * 8 + grp) * 68 + ks * 8 + tg];
                uint32_t b0 = p[0], b1 = p[4];
                mma_tf32(s[0][nt], a[0], b0, b1);
                mma_tf32(s[1][nt], a[1], b0, b1);
            }
        }

        // ---- exp2, accumulate l, stash P (no max/rescale needed) ----
        #pragma unroll
        for (int mt = 0; mt < 2; ++mt) {
            #pragma unroll
            for (int nt = 0; nt < 8; ++nt) {
                float p0 = exp2a(s[mt][nt][0]);
                float p1 = exp2a(s[mt][nt][1]);
                float p2 = exp2a(s[mt][nt][2]);
                float p3 = exp2a(s[mt][nt][3]);
                lacc[mt][0] += p0 + p1;
                lacc[mt][1] += p2 + p3;
                uint32_t* pp = &Ps[(row0 + mt * 16 + grp) * 68 + nt * 8 + tg * 2];
                pp[0]          = f2tf(p0);
                pp[1]          = f2tf(p1);
                pp[68 * 8]     = f2tf(p2);
                pp[68 * 8 + 1] = f2tf(p3);
            }
        }
        __syncwarp();   // P written/read by this warp's rows only

        // ---- O += P V ----
        #pragma unroll
        for (int ks = 0; ks < 8; ++ks) {
            uint32_t a[2][4];
            #pragma unroll
            for (int mt = 0; mt < 2; ++mt) {
                const uint32_t* p = &Ps[(row0 + mt * 16 + grp) * 68 + ks * 8 + tg];
                a[mt][0] = p[0];       a[mt][2] = p[4];
                a[mt][1] = p[68 * 8];  a[mt][3] = p[68 * 8 + 4];
            }
            #pragma unroll
            for (int nt = 0; nt < 8; ++nt) {
                uint32_t b0 = Vs[(ks * 8 + tg) * 72 + nt * 8 + grp];
                uint32_t b1 = Vs[(ks * 8 + tg + 4) * 72 + nt * 8 + grp];
                mma_tf32(o[0][nt], a[0], b0, b1);
                mma_tf32(o[1][nt], a[1], b0, b1);
            }
        }
    }

    // epilogue: reduce l across the quad, normalize, store
    #pragma unroll
    for (int mt = 0; mt < 2; ++mt) {
        float l0 = lacc[mt][0], l1 = lacc[mt][1];
        l0 += __shfl_xor_sync(0xffffffffu, l0, 1);
        l0 += __shfl_xor_sync(0xffffffffu, l0, 2);
        l1 += __shfl_xor_sync(0xffffffffu, l1, 1);
        l1 += __shfl_xor_sync(0xffffffffu, l1, 2);
        float inv0 = 1.0f / l0;
        float inv1 = 1.0f / l1;
        int row = qrow0 + row0 + mt * 16 + grp;
        #pragma unroll
        for (int nt = 0; nt < 8; ++nt) {
            int col = hoff + nt * 8 + tg * 2;
            *(float2*)&g_o[(size_t)row * Dm + col] =
                make_float2(o[mt][nt][0] * inv0, o[mt][nt][1] * inv0);
            *(float2*)&g_o[(size_t)(row + 8) * Dm + col] =
                make_float2(o[mt][nt][2] * inv1, o[mt][nt][3] * inv1);
        }
    }
}

// ---------------------------------------------------------------------------
extern "C" void kernel_launch(void* const* d_in, const int* in_sizes, int n_in,
                              void* d_out, int out_size)
{
    (void)in_sizes; (void)n_in; (void)out_size;
    const float* x    = (const float*)d_in[0];
    const float* Wq   = (const float*)d_in[1];
    const float* Wkv  = (const float*)d_in[2];
    const float* Wout = (const float*)d_in[3];
    float* out = (float*)d_out;

    float *q, *k, *v, *o;
    cudaGetSymbolAddress((void**)&q, g_q);
    cudaGetSymbolAddress((void**)&k, g_k);
    cudaGetSymbolAddress((void**)&v, g_v);
    cudaGetSymbolAddress((void**)&o, g_o);

    cudaFuncSetAttribute(attn_tf32,
                         cudaFuncAttributeMaxDynamicSharedMemorySize, 105472);

    dim3 blk(256);
    dim3 ggrid(Dm / 64, Rows / 128);   // (8, 32) = 256 CTAs

    // Projections (tf32 tensor cores). RMS-norm fused into Q/K epilogues:
    // Q also folds scale*log2e so softmax runs directly in exp2 domain.
    gemm_tf32<<<ggrid, blk>>>(x, Wq, q, Rows, Dm, Dm, SCALEv * LOG2E);
    gemm_tf32<<<ggrid, blk>>>(x, Wkv, k, Rows, Dm, Dm, 1.0f);
    gemm_tf32<<<ggrid, blk>>>(x, Wkv + (size_t)Dm * Dm, v, Rows, Dm, Dm, 0.0f);

    // Attention: 256 CTAs (128 queries each), 2 CTAs/SM
    attn_tf32<<<dim3(Sn / 128, Hh, Bb), 128, 105472>>>();

    // Output projection
    gemm_tf32<<<ggrid, blk>>>(o, Wout, out, Rows, Dm, Dm, 0.0f);
}